// round 14
// baseline (speedup 1.0000x reference)
#include <cuda_runtime.h>
#include <cstdint>

#define ROWS        8192
#define COLS        32768
#define K_TOP       32
#define PRE_THRESH  2.8f

#define NTH         512
#define VEC         8                       // floats per access (256-bit)
#define ITERS       (COLS / VEC / NTH)      // 8 v8-accesses per thread
#define BATCH       2                       // front-batched v8 loads per group
#define GROUPS      (ITERS / BATCH)         // 4
#define CAND_CAP    192                     // mean ~84, sigma ~9.1 -> 11.8 sigma

__device__ __forceinline__ unsigned fmap(float f) {
    unsigned b = __float_as_uint(f);
    return (b & 0x80000000u) ? ~b : (b | 0x80000000u);
}
__device__ __forceinline__ float unfmap(unsigned u) {
    unsigned b = (u & 0x80000000u) ? (u ^ 0x80000000u) : ~u;
    return __uint_as_float(b);
}
// unique key: value desc, index asc tiebreak (matches jax.lax.top_k)
__device__ __forceinline__ unsigned long long make_key(float v, int idx) {
    return ((unsigned long long)fmap(v) << 32) | (unsigned)(~idx);
}

// 256-bit streaming global load (sm_100+)
__device__ __forceinline__ void ldg8_cs(const float* p, float* v) {
    asm volatile("ld.global.cs.v8.f32 {%0,%1,%2,%3,%4,%5,%6,%7}, [%8];"
                 : "=f"(v[0]), "=f"(v[1]), "=f"(v[2]), "=f"(v[3]),
                   "=f"(v[4]), "=f"(v[5]), "=f"(v[6]), "=f"(v[7])
                 : "l"(p));
}

// warp-aggregated histogram add (fallback path only)
__device__ __forceinline__ void hist_add(int* hist, int digit) {
    const unsigned act   = __activemask();
    const unsigned peers = __match_any_sync(act, digit);
    const int      lane  = threadIdx.x & 31;
    if ((__ffs(peers) - 1) == lane)
        atomicAdd(&hist[digit], __popc(peers));
}

// ---------------------------------------------------------------------------
// Pure-read kernel: 1 CTA per row. Output already zeroed by memset, so this
// is a read-only 1 GiB stream + candidate gather + inline rank-select +
// ~1 MB scatter. No zero-stores -> no read/write bus mixing.
// ---------------------------------------------------------------------------
__global__ __launch_bounds__(NTH) void topk_kernel(
    const float* __restrict__ x, float* __restrict__ out)
{
    __shared__ __align__(16) unsigned long long s_keys[CAND_CAP + 2];
    __shared__ int s_cnt;
    __shared__ int s_hist[256];
    __shared__ int s_digit, s_want, s_bcnt;

    const int row = blockIdx.x;
    const size_t row_off = (size_t)row * COLS;
    const int tid = threadIdx.x;

    if (tid == 0) s_cnt = 0;
    __syncthreads();

    const float* __restrict__ xin = x + row_off;

    // ------------- Phase 1: pure read stream (front-batched v8 groups) -----
    #pragma unroll
    for (int g = 0; g < GROUPS; g++) {
        float v[BATCH][VEC];
        #pragma unroll
        for (int k = 0; k < BATCH; k++)
            ldg8_cs(xin + (tid + (g * BATCH + k) * NTH) * VEC, v[k]);
        #pragma unroll
        for (int k = 0; k < BATCH; k++) {
            const int gidx = (tid + (g * BATCH + k) * NTH) * VEC;
            #pragma unroll
            for (int e = 0; e < VEC; e++) {
                if (v[k][e] >= PRE_THRESH) {
                    int p = atomicAdd(&s_cnt, 1);
                    if (p < CAND_CAP) s_keys[p] = make_key(v[k][e], gidx + e);
                }
            }
        }
    }
    __syncthreads();

    const int cnt = s_cnt;
    // zero-pad the odd slot so the LDS.128 pair loop is exact (0 < any key)
    if (tid == 0 && (cnt & 1) && cnt < CAND_CAP) s_keys[cnt] = 0;
    __syncthreads();

    const bool fast = (cnt >= K_TOP) && (cnt <= CAND_CAP);

    if (fast) {
        // ------------- Phase 2: rank-select over unique keys (inline) ------
        if (tid < cnt) {
            const unsigned long long k0 = s_keys[tid];
            const ulonglong2* __restrict__ kv =
                reinterpret_cast<const ulonglong2*>(s_keys);
            const int nh = (cnt + 1) >> 1;
            int r0 = 0;
            #pragma unroll 4
            for (int j = 0; j < nh; j++) {
                const ulonglong2 p = kv[j];          // LDS.128 broadcast
                r0 += (int)(p.x > k0) + (int)(p.y > k0);
            }
            if (r0 < K_TOP) {
                const int idx = (int)(~(unsigned)k0) & (COLS - 1);
                out[row_off + idx] = fmaxf(unfmap((unsigned)(k0 >> 32)), 0.f);
            }
        }
    } else {
        // ------------- Fallback: in-block full-row radix (exact) -----------
        unsigned long long prefix = 0, T = 0;
        int want = K_TOP;
        for (int shift = 56; shift >= 0; shift -= 8) {
            if (tid < 256) s_hist[tid] = 0;
            __syncthreads();
            for (int j = tid; j < COLS; j += NTH) {
                unsigned long long key = make_key(x[row_off + j], j);
                if (shift == 56 || (key >> (shift + 8)) == prefix)
                    hist_add(s_hist, (int)((key >> shift) & 255));
            }
            __syncthreads();
            if (tid == 0) {
                int acc = 0, d = 255;
                for (; d >= 0; d--) {
                    if (acc + s_hist[d] >= want) break;
                    acc += s_hist[d];
                }
                if (d < 0) d = 0;
                s_digit = d; s_want = want - acc; s_bcnt = s_hist[d];
            }
            __syncthreads();
            prefix = (prefix << 8) | (unsigned long long)s_digit;
            want   = s_want;
            const int c = s_bcnt;
            if (want == c) { T = prefix << shift; break; }
            __syncthreads();
            // unique keys -> at shift==0, c==1==want, so the break always fires
        }
        for (int j = tid; j < COLS; j += NTH) {
            unsigned long long key = make_key(x[row_off + j], j);
            if (key >= T) {
                const int idx = (int)(~(unsigned)key) & (COLS - 1);
                out[row_off + idx] = fmaxf(unfmap((unsigned)(key >> 32)), 0.f);
            }
        }
    }
}

extern "C" void kernel_launch(void* const* d_in, const int* in_sizes, int n_in,
                              void* d_out, int out_size)
{
    const float* x = (const float*)d_in[0];
    float* out = (float*)d_out;
    // Phase A: pure write stream (driver memset kernel) zeroes the output.
    cudaMemsetAsync(d_out, 0, (size_t)out_size * sizeof(float));
    // Phase B: pure read stream + select + sparse scatter (same stream ->
    // ordered after the memset; both are graph-capturable).
    topk_kernel<<<ROWS, NTH>>>(x, out);
}

// round 16
// speedup vs baseline: 1.0222x; 1.0222x over previous
#include <cuda_runtime.h>
#include <cstdint>

#define ROWS        8192
#define COLS        32768
#define K_TOP       32
#define PRE_THRESH  2.8f

#define NTH         512
#define VEC         8                       // floats per access (256-bit)
#define ITERS       (COLS / VEC / NTH)      // 8 v8-accesses per thread
#define BATCH       2                       // front-batched v8 loads per group
#define GROUPS      (ITERS / BATCH)         // 4
#define CAND_CAP    192                     // mean ~84, sigma ~9.1 -> 11.8 sigma

#define ZCHUNK_FLOATS 4096                  // 16 KB smem zero buffer
#define ZCHUNKS       (COLS / ZCHUNK_FLOATS) // 8 bulk stores per row

__device__ __forceinline__ unsigned fmap(float f) {
    unsigned b = __float_as_uint(f);
    return (b & 0x80000000u) ? ~b : (b | 0x80000000u);
}
__device__ __forceinline__ float unfmap(unsigned u) {
    unsigned b = (u & 0x80000000u) ? (u ^ 0x80000000u) : ~u;
    return __uint_as_float(b);
}
// unique key: value desc, index asc tiebreak (matches jax.lax.top_k)
__device__ __forceinline__ unsigned long long make_key(float v, int idx) {
    return ((unsigned long long)fmap(v) << 32) | (unsigned)(~idx);
}

// 256-bit streaming global load (sm_100+)
__device__ __forceinline__ void ldg8_cs(const float* p, float* v) {
    asm volatile("ld.global.cs.v8.f32 {%0,%1,%2,%3,%4,%5,%6,%7}, [%8];"
                 : "=f"(v[0]), "=f"(v[1]), "=f"(v[2]), "=f"(v[3]),
                   "=f"(v[4]), "=f"(v[5]), "=f"(v[6]), "=f"(v[7])
                 : "l"(p));
}

__device__ __forceinline__ uint32_t smem_u32(const void* p) {
    uint32_t a;
    asm("{ .reg .u64 t; cvta.to.shared.u64 t, %1; cvt.u32.u64 %0, t; }"
        : "=r"(a) : "l"(p));
    return a;
}

// warp-aggregated histogram add (fallback path only)
__device__ __forceinline__ void hist_add(int* hist, int digit) {
    const unsigned act   = __activemask();
    const unsigned peers = __match_any_sync(act, digit);
    const int      lane  = threadIdx.x & 31;
    if ((__ffs(peers) - 1) == lane)
        atomicAdd(&hist[digit], __popc(peers));
}

// ---------------------------------------------------------------------------
// Monolithic, TMA-offloaded writes: 1 CTA per row. Zero-stores issued as 8
// cp.async.bulk S->G transfers from a 16 KB smem zero buffer (async path);
// LDG/LSU path carries only the v8 read stream + candidate gather. Inline
// rank-select + scatter after bulk-store completion. No global scratch.
// ---------------------------------------------------------------------------
__global__ __launch_bounds__(NTH) void topk_kernel(
    const float* __restrict__ x, float* __restrict__ out)
{
    __shared__ __align__(128) float s_zero[ZCHUNK_FLOATS];   // 16 KB of zeros
    __shared__ __align__(16) unsigned long long s_keys[CAND_CAP + 2];
    __shared__ int s_cnt;
    __shared__ int s_hist[256];
    __shared__ int s_digit, s_want, s_bcnt;

    const int row = blockIdx.x;
    const size_t row_off = (size_t)row * COLS;
    const int tid  = threadIdx.x;
    const int lane = tid & 31;
    const int warp = tid >> 5;

    if (tid == 0) s_cnt = 0;
    // zero the smem buffer (float4 stores)
    {
        float4* z4 = reinterpret_cast<float4*>(s_zero);
        #pragma unroll
        for (int i = tid; i < ZCHUNK_FLOATS / 4; i += NTH)
            z4[i] = make_float4(0.f, 0.f, 0.f, 0.f);
    }
    __syncthreads();

    float* __restrict__ zo = out + row_off;

    // Issue the row's zero-fill as 8 async bulk stores (warps 0..7, lane 0).
    const bool issuer = (lane == 0) && (warp < ZCHUNKS);
    if (issuer) {
        asm volatile("fence.proxy.async;" ::: "memory");  // smem zeros -> async proxy
        const uint32_t src = smem_u32(s_zero);
        float* dst = zo + (size_t)warp * ZCHUNK_FLOATS;
        asm volatile(
            "cp.async.bulk.global.shared::cta.bulk_group [%0], [%1], %2;"
            :: "l"(dst), "r"(src), "r"((unsigned)(ZCHUNK_FLOATS * 4))
            : "memory");
        asm volatile("cp.async.bulk.commit_group;" ::: "memory");
    }

    const float* __restrict__ xin = x + row_off;

    // ------------- Phase 1: pure-LDG read stream + candidate gather --------
    #pragma unroll
    for (int g = 0; g < GROUPS; g++) {
        float v[BATCH][VEC];
        #pragma unroll
        for (int k = 0; k < BATCH; k++)
            ldg8_cs(xin + (tid + (g * BATCH + k) * NTH) * VEC, v[k]);
        #pragma unroll
        for (int k = 0; k < BATCH; k++) {
            const int gidx = (tid + (g * BATCH + k) * NTH) * VEC;
            #pragma unroll
            for (int e = 0; e < VEC; e++) {
                if (v[k][e] >= PRE_THRESH) {
                    int p = atomicAdd(&s_cnt, 1);
                    if (p < CAND_CAP) s_keys[p] = make_key(v[k][e], gidx + e);
                }
            }
        }
    }

    // Complete the zero-fill before any winner scatter (same CTA, same row).
    if (issuer) {
        asm volatile("cp.async.bulk.wait_group 0;" ::: "memory");
        asm volatile("fence.proxy.async;" ::: "memory");  // async writes -> generic
    }
    __syncthreads();

    const int cnt = s_cnt;
    // zero-pad the odd slot so the LDS.128 pair loop is exact (0 < any key)
    if (tid == 0 && (cnt & 1) && cnt < CAND_CAP) s_keys[cnt] = 0;
    __syncthreads();

    const bool fast = (cnt >= K_TOP) && (cnt <= CAND_CAP);

    if (fast) {
        // ------------- Phase 2: rank-select over unique keys (inline) ------
        if (tid < cnt) {
            const unsigned long long k0 = s_keys[tid];
            const ulonglong2* __restrict__ kv =
                reinterpret_cast<const ulonglong2*>(s_keys);
            const int nh = (cnt + 1) >> 1;
            int r0 = 0;
            #pragma unroll 4
            for (int j = 0; j < nh; j++) {
                const ulonglong2 p = kv[j];          // LDS.128 broadcast
                r0 += (int)(p.x > k0) + (int)(p.y > k0);
            }
            if (r0 < K_TOP) {
                const int idx = (int)(~(unsigned)k0) & (COLS - 1);
                out[row_off + idx] = fmaxf(unfmap((unsigned)(k0 >> 32)), 0.f);
            }
        }
    } else {
        // ------------- Fallback: in-block full-row radix (exact) -----------
        unsigned long long prefix = 0, T = 0;
        int want = K_TOP;
        for (int shift = 56; shift >= 0; shift -= 8) {
            if (tid < 256) s_hist[tid] = 0;
            __syncthreads();
            for (int j = tid; j < COLS; j += NTH) {
                unsigned long long key = make_key(x[row_off + j], j);
                if (shift == 56 || (key >> (shift + 8)) == prefix)
                    hist_add(s_hist, (int)((key >> shift) & 255));
            }
            __syncthreads();
            if (tid == 0) {
                int acc = 0, d = 255;
                for (; d >= 0; d--) {
                    if (acc + s_hist[d] >= want) break;
                    acc += s_hist[d];
                }
                if (d < 0) d = 0;
                s_digit = d; s_want = want - acc; s_bcnt = s_hist[d];
            }
            __syncthreads();
            prefix = (prefix << 8) | (unsigned long long)s_digit;
            want   = s_want;
            const int c = s_bcnt;
            if (want == c) { T = prefix << shift; break; }
            __syncthreads();
            // unique keys -> at shift==0, c==1==want, so the break always fires
        }
        for (int j = tid; j < COLS; j += NTH) {
            unsigned long long key = make_key(x[row_off + j], j);
            if (key >= T) {
                const int idx = (int)(~(unsigned)key) & (COLS - 1);
                out[row_off + idx] = fmaxf(unfmap((unsigned)(key >> 32)), 0.f);
            }
        }
    }
}

extern "C" void kernel_launch(void* const* d_in, const int* in_sizes, int n_in,
                              void* d_out, int out_size)
{
    const float* x = (const float*)d_in[0];
    float* out = (float*)d_out;
    topk_kernel<<<ROWS, NTH>>>(x, out);
}